// round 14
// baseline (speedup 1.0000x reference)
#include <cuda_runtime.h>
#include <cuda_bf16.h>
#include <math.h>
#include <stdint.h>

// Problem constants
#define BATCH   2
#define SEQ     2048
#define EMB     2048
#define NHEAD   16
#define HDIM    128
#define MTOT    (BATCH*SEQ)          // 4096
#define GK      2048
#define GN      2048
#define ATT_SCALE 0.08838834764831845f  // 1/sqrt(128)

// Scratch (device globals: allocation-free)
__device__ float g_cos[SEQ*(HDIM/2)];
__device__ float g_sin[SEQ*(HDIM/2)];
__device__ __nv_bfloat16 g_Ahi[MTOT*GK];
__device__ __nv_bfloat16 g_Alo[MTOT*GK];
__device__ __nv_bfloat16 g_Whi[4*GN*GK];   // wq,wk,wv,wo in [K,N], hi
__device__ __nv_bfloat16 g_Wlo[4*GN*GK];   // lo
__device__ __nv_bfloat16 g_Qhi[MTOT*EMB];
__device__ __nv_bfloat16 g_Qlo[MTOT*EMB];
__device__ __nv_bfloat16 g_Khi[MTOT*EMB];
__device__ __nv_bfloat16 g_Klo[MTOT*EMB];
__device__ __nv_bfloat16 g_Vhi[MTOT*EMB];   // [b,s,h,d]
__device__ __nv_bfloat16 g_Vlo[MTOT*EMB];
__device__ __nv_bfloat16 g_Vthi[MTOT*EMB];  // [b,h,d,s]
__device__ __nv_bfloat16 g_Vtlo[MTOT*EMB];
__device__ __nv_bfloat16 g_Yhi[MTOT*EMB];
__device__ __nv_bfloat16 g_Ylo[MTOT*EMB];

// ============================================================================
// PTX helpers (portable sm_80+ only)
// ============================================================================
__device__ __forceinline__ uint32_t smem_u32(const void* p) {
    uint32_t a;
    asm("{ .reg .u64 t; cvta.to.shared.u64 t, %1; cvt.u32.u64 %0, t; }"
        : "=r"(a) : "l"(p));
    return a;
}

#define CP_ASYNC16(dst, src) \
    asm volatile("cp.async.cg.shared.global [%0], [%1], 16;" \
                 :: "r"(dst), "l"(src) : "memory")
#define CP_COMMIT() asm volatile("cp.async.commit_group;" ::: "memory")
#define CP_WAIT1()  asm volatile("cp.async.wait_group 1;" ::: "memory")
#define CP_WAIT0()  asm volatile("cp.async.wait_group 0;" ::: "memory")

#define LDSM4(r, addr)                                                         \
    asm volatile("ldmatrix.sync.aligned.m8n8.x4.shared.b16 {%0,%1,%2,%3}, [%4];" \
                 : "=r"((r)[0]), "=r"((r)[1]), "=r"((r)[2]), "=r"((r)[3])      \
                 : "r"(addr))

#define LDSM4T(r, addr)                                                        \
    asm volatile("ldmatrix.sync.aligned.m8n8.x4.trans.shared.b16 {%0,%1,%2,%3}, [%4];" \
                 : "=r"((r)[0]), "=r"((r)[1]), "=r"((r)[2]), "=r"((r)[3])      \
                 : "r"(addr))

#define MMA16816(d, a, b)                                                      \
    asm volatile(                                                              \
        "mma.sync.aligned.m16n8k16.row.col.f32.bf16.bf16.f32 "                 \
        "{%0,%1,%2,%3}, {%4,%5,%6,%7}, {%8,%9}, {%0,%1,%2,%3};"                \
        : "+f"((d)[0]), "+f"((d)[1]), "+f"((d)[2]), "+f"((d)[3])               \
        : "r"((a)[0]), "r"((a)[1]), "r"((a)[2]), "r"((a)[3]),                  \
          "r"((b)[0]), "r"((b)[1]))

__device__ __forceinline__ uint32_t pack_bf16x2(__nv_bfloat16 x, __nv_bfloat16 y) {
    __nv_bfloat162 v(x, y);
    return *reinterpret_cast<uint32_t*>(&v);
}

// A tile: [rows][64B], 4 slots of 16B, swizzle period-8
__device__ __forceinline__ uint32_t tile_off(uint32_t row, uint32_t slot) {
    return row * 64 + ((slot ^ ((row >> 1) & 3)) << 4);
}
// B tile: [rows][256B], 16 slots of 16B, swizzle period-8
__device__ __forceinline__ uint32_t btile_off(uint32_t row, uint32_t slot) {
    return row * 256 + ((slot ^ (row & 7)) << 4);
}

__device__ __forceinline__ void split1(float v, __nv_bfloat16& h, __nv_bfloat16& l) {
    h = __float2bfloat16(v);
    l = __float2bfloat16(v - __bfloat162float(h));
}

// ============================================================================
// Fused split: z=0 -> x, z=1..4 -> weights ([K,N])
// ============================================================================
__global__ void split_multi(const float* __restrict__ x,
                            const float* __restrict__ wq, const float* __restrict__ wk,
                            const float* __restrict__ wv, const float* __restrict__ wo,
                            __nv_bfloat16* __restrict__ ahi, __nv_bfloat16* __restrict__ alo,
                            __nv_bfloat16* __restrict__ whi, __nv_bfloat16* __restrict__ wlo) {
    int z = blockIdx.z;
    const float* src;
    __nv_bfloat16 *dh, *dl;
    int n4;
    if (z == 0) { src = x; dh = ahi; dl = alo; n4 = MTOT * GK / 4; }
    else {
        src = (z == 1) ? wq : (z == 2) ? wk : (z == 3) ? wv : wo;
        dh = whi + (size_t)(z - 1) * GN * GK;
        dl = wlo + (size_t)(z - 1) * GN * GK;
        n4 = GN * GK / 4;
    }
    int i = blockIdx.x * blockDim.x + threadIdx.x;
    if (i >= n4) return;
    float4 v = ((const float4*)src)[i];
    __nv_bfloat16 h0, h1, h2, h3, l0, l1, l2, l3;
    split1(v.x, h0, l0); split1(v.y, h1, l1);
    split1(v.z, h2, l2); split1(v.w, h3, l3);
    __nv_bfloat162* hp = (__nv_bfloat162*)dh;
    __nv_bfloat162* lp = (__nv_bfloat162*)dl;
    hp[i*2+0] = __nv_bfloat162(h0, h1);
    hp[i*2+1] = __nv_bfloat162(h2, h3);
    lp[i*2+0] = __nv_bfloat162(l0, l1);
    lp[i*2+1] = __nv_bfloat162(l2, l3);
}

// ---------------------------------------------------------------------------
// RoPE table
// ---------------------------------------------------------------------------
__global__ void rope_table_kernel(float* ct, float* st) {
    int idx = blockIdx.x * blockDim.x + threadIdx.x;
    if (idx >= SEQ * (HDIM/2)) return;
    int s = idx >> 6;
    int j = idx & 63;
    float inv = powf(10000.0f, -((float)(2*j)) / 128.0f);
    float a = (float)s * inv;
    ct[idx] = cosf(a);
    st[idx] = sinf(a);
}

// ---------------------------------------------------------------------------
// V bf16 [b,s,h,d] -> Vt bf16 [b,h,d,s] (hi and lo)
// ---------------------------------------------------------------------------
__global__ void vtrans_bf16(const __nv_bfloat16* __restrict__ Vhi,
                            const __nv_bfloat16* __restrict__ Vlo,
                            __nv_bfloat16* __restrict__ Thi,
                            __nv_bfloat16* __restrict__ Tlo) {
    __shared__ __nv_bfloat16 th[32][34], tl[32][34];
    int s0 = blockIdx.x * 32, d0 = blockIdx.y * 32, bh = blockIdx.z;
    int b = bh >> 4, h = bh & 15;
    int tx = threadIdx.x, ty = threadIdx.y;
    #pragma unroll
    for (int j = 0; j < 32; j += 8) {
        size_t o = (size_t)(b * SEQ + s0 + ty + j) * EMB + h * HDIM + d0 + tx;
        th[ty + j][tx] = Vhi[o];
        tl[ty + j][tx] = Vlo[o];
    }
    __syncthreads();
    #pragma unroll
    for (int j = 0; j < 32; j += 8) {
        size_t o = (size_t)(bh * HDIM + d0 + ty + j) * SEQ + s0 + tx;
        Thi[o] = th[tx][ty + j];
        Tlo[o] = tl[tx][ty + j];
    }
}

// ============================================================================
// Shared GEMM mainloop (split-bf16, 3 terms), 3-stage cp.async pipeline.
// ============================================================================
#define NKB (GK / 32)
#define G_STAGE 32768
#define GEMM_SMEM_BYTES (3*G_STAGE)

__device__ __forceinline__ void gemm_mainloop(
    const __nv_bfloat16* __restrict__ Ahi, const __nv_bfloat16* __restrict__ Alo,
    const __nv_bfloat16* __restrict__ Bhi, const __nv_bfloat16* __restrict__ Blo,
    uint32_t base, int tid, int m0, int n0, float (&acc)[4][4][4]) {
    const int wid  = tid >> 5;
    const int lane = tid & 31;
    const int wm = wid >> 2;
    const int wn = wid & 3;

    #pragma unroll
    for (int mt = 0; mt < 4; mt++)
        #pragma unroll
        for (int nt = 0; nt < 4; nt++)
            #pragma unroll
            for (int e = 0; e < 4; e++) acc[mt][nt][e] = 0.0f;

    const uint32_t a_row  = wm * 64 + (lane & 15);
    const int      a_kadd = lane >> 4;
    const uint32_t b_row16 = lane & 15;
    const uint32_t b_sadd  = lane >> 4;

    auto issue = [&](int kb) {
        const int kcol = kb * 32;
        const uint32_t stg = base + (kb % 3) * G_STAGE;
        #pragma unroll
        for (int i = 0; i < 2; i++) {
            int c = i * 256 + tid;
            {
                uint32_t row = c >> 2, slot = c & 3;
                const __nv_bfloat16* s = Ahi + (size_t)(m0 + row) * GK + kcol + slot * 8;
                const __nv_bfloat16* s2 = Alo + (size_t)(m0 + row) * GK + kcol + slot * 8;
                uint32_t d = stg + tile_off(row, slot);
                CP_ASYNC16(d, s);
                CP_ASYNC16(d + 8192, s2);
            }
            {
                uint32_t row = c >> 4, slot = c & 15;
                const __nv_bfloat16* s = Bhi + (size_t)(kcol + row) * GN + n0 + slot * 8;
                const __nv_bfloat16* s2 = Blo + (size_t)(kcol + row) * GN + n0 + slot * 8;
                uint32_t d = stg + 16384 + btile_off(row, slot);
                CP_ASYNC16(d, s);
                CP_ASYNC16(d + 8192, s2);
            }
        }
        CP_COMMIT();
    };

    issue(0);
    issue(1);

    for (int kb = 0; kb < NKB; kb++) {
        if (kb < NKB - 1) CP_WAIT1(); else CP_WAIT0();
        __syncthreads();
        if (kb + 2 < NKB) issue(kb + 2);

        const uint32_t st = base + (kb % 3) * G_STAGE;

        #pragma unroll
        for (int ks = 0; ks < 2; ks++) {
            uint32_t ahi[4][4], alo[4][4], bhi[4][2], blo[4][2];
            #pragma unroll
            for (int mt = 0; mt < 4; mt++) {
                uint32_t row = a_row + mt * 16;
                uint32_t ad  = st + tile_off(row, (uint32_t)(ks * 2 + a_kadd));
                LDSM4(ahi[mt], ad);
                LDSM4(alo[mt], ad + 8192);
            }
            #pragma unroll
            for (int np = 0; np < 2; np++) {
                uint32_t row = ks * 16 + b_row16;
                uint32_t slot = wn * 4 + np * 2 + b_sadd;
                uint32_t bd = st + 16384 + btile_off(row, slot);
                uint32_t r[4];
                LDSM4T(r, bd);
                bhi[np*2][0] = r[0]; bhi[np*2][1] = r[1];
                bhi[np*2+1][0] = r[2]; bhi[np*2+1][1] = r[3];
                LDSM4T(r, bd + 8192);
                blo[np*2][0] = r[0]; blo[np*2][1] = r[1];
                blo[np*2+1][0] = r[2]; blo[np*2+1][1] = r[3];
            }
            #pragma unroll
            for (int mt = 0; mt < 4; mt++)
                #pragma unroll
                for (int nt = 0; nt < 4; nt++) {
                    MMA16816(acc[mt][nt], ahi[mt], bhi[nt]);
                    MMA16816(acc[mt][nt], ahi[mt], blo[nt]);
                    MMA16816(acc[mt][nt], alo[mt], bhi[nt]);
                }
        }
    }
}

// ---- QKV GEMM: z=0 Q(rope), z=1 K(rope), z=2 V(plain split) ----
__global__ __launch_bounds__(256) void qkv_gemm(
    const __nv_bfloat16* __restrict__ Ahi, const __nv_bfloat16* __restrict__ Alo,
    const __nv_bfloat16* __restrict__ Whi, const __nv_bfloat16* __restrict__ Wlo,
    const float* __restrict__ ct, const float* __restrict__ st,
    __nv_bfloat16* __restrict__ Qhi, __nv_bfloat16* __restrict__ Qlo,
    __nv_bfloat16* __restrict__ Khi, __nv_bfloat16* __restrict__ Klo,
    __nv_bfloat16* __restrict__ Vhi, __nv_bfloat16* __restrict__ Vlo) {
    extern __shared__ char smraw[];
    const uint32_t base = smem_u32(smraw);
    const int tid = threadIdx.x;
    const int m0 = blockIdx.y * 128;
    const int n0 = blockIdx.x * 128;
    const int z  = blockIdx.z;
    const __nv_bfloat16* Bh = Whi + (size_t)z * GN * GK;
    const __nv_bfloat16* Bl = Wlo + (size_t)z * GN * GK;

    float acc[4][4][4];
    gemm_mainloop(Ahi, Alo, Bh, Bl, base, tid, m0, n0, acc);

    const int wid = tid >> 5, lane = tid & 31;
    const int wm = wid >> 2, wn = wid & 3;
    const int r0 = m0 + wm * 64 + (lane >> 2);
    const int c0 = n0 + wn * 32 + (lane & 3) * 2;
    __nv_bfloat16* Hi = (z == 0) ? Qhi : (z == 1) ? Khi : Vhi;
    __nv_bfloat16* Lo = (z == 0) ? Qlo : (z == 1) ? Klo : Vlo;
    const bool dorope = (z < 2);

    #pragma unroll
    for (int mt = 0; mt < 4; mt++)
        #pragma unroll
        for (int nt = 0; nt < 4; nt++) {
            int col = c0 + nt * 8;
            int j = (col & 127) >> 1;
            #pragma unroll
            for (int rr = 0; rr < 2; rr++) {
                int row = r0 + mt * 16 + rr * 8;
                float x1 = acc[mt][nt][rr*2], x2 = acc[mt][nt][rr*2+1];
                if (dorope) {
                    int s = row & (SEQ - 1);
                    float cv = ct[(s << 6) + j], sv = st[(s << 6) + j];
                    float n1 = x1 * cv - x2 * sv;
                    float n2 = x1 * sv + x2 * cv;
                    x1 = n1; x2 = n2;
                }
                __nv_bfloat16 h1, h2, l1, l2;
                split1(x1, h1, l1); split1(x2, h2, l2);
                size_t o = (size_t)row * EMB + col;
                *(uint32_t*)(Hi + o) = pack_bf16x2(h1, h2);
                *(uint32_t*)(Lo + o) = pack_bf16x2(l1, l2);
            }
        }
}

// ---- Output GEMM: fp32 epilogue ----
__global__ __launch_bounds__(256) void out_gemm(
    const __nv_bfloat16* __restrict__ Ahi, const __nv_bfloat16* __restrict__ Alo,
    const __nv_bfloat16* __restrict__ Bhi, const __nv_bfloat16* __restrict__ Blo,
    float* __restrict__ C) {
    extern __shared__ char smraw[];
    const uint32_t base = smem_u32(smraw);
    const int tid = threadIdx.x;
    const int m0 = blockIdx.y * 128;
    const int n0 = blockIdx.x * 128;

    float acc[4][4][4];
    gemm_mainloop(Ahi, Alo, Bhi, Blo, base, tid, m0, n0, acc);

    const int wid = tid >> 5, lane = tid & 31;
    const int wm = wid >> 2, wn = wid & 3;
    const int r0  = m0 + wm * 64 + (lane >> 2);
    const int col = n0 + wn * 32 + (lane & 3) * 2;
    #pragma unroll
    for (int mt = 0; mt < 4; mt++)
        #pragma unroll
        for (int nt = 0; nt < 4; nt++) {
            float* d = acc[mt][nt];
            size_t o0 = (size_t)(r0 + mt * 16)     * GN + col + nt * 8;
            size_t o1 = (size_t)(r0 + mt * 16 + 8) * GN + col + nt * 8;
            *(float2*)(C + o0) = make_float2(d[0], d[1]);
            *(float2*)(C + o1) = make_float2(d[2], d[3]);
        }
}

// ============================================================================
// Tensor-core causal flash attention (split-bf16, 3-term).
// BQ=128 (8 warps x m16), BK=64, double-buffered K/Vt, Q resident in smem.
// V pre-transposed [b,h,d,s], consumed with non-trans LDSM (R11 layout).
// Heavy CTAs launch first (reversed qb); fully-masked warp-tiles skipped.
// smem: Qhi/Qlo @ 0/32768; stage s @ 65536+s*65536:
//       Khi(16K) Klo(16K) Vthi(16K) Vtlo(16K)
// ============================================================================
#define ATTN_Q_BYTES     65536
#define ATTN_STAGE_BYTES 65536
#define ATTN_SMEM_BYTES  (ATTN_Q_BYTES + 2*ATTN_STAGE_BYTES)  // 196608

__global__ __launch_bounds__(256, 1) void attn_mma(
    const __nv_bfloat16* __restrict__ Qhi, const __nv_bfloat16* __restrict__ Qlo,
    const __nv_bfloat16* __restrict__ Khi, const __nv_bfloat16* __restrict__ Klo,
    const __nv_bfloat16* __restrict__ Vthi, const __nv_bfloat16* __restrict__ Vtlo,
    __nv_bfloat16* __restrict__ Yhi, __nv_bfloat16* __restrict__ Ylo) {
    extern __shared__ char smraw[];
    const uint32_t base = smem_u32(smraw);
    const int tid = threadIdx.x, wid = tid >> 5, lane = tid & 31;
    const int qb = gridDim.x - 1 - blockIdx.x;   // heavy CTAs first
    const int h = blockIdx.y, b = blockIdx.z;
    const int q0 = qb * 128;
    const int wm0 = wid * 16;
    const int g = lane >> 2, t4 = lane & 3;
    const int ntiles = 2 * qb + 2;

    const uint32_t a_row = wm0 + (lane & 15);
    const int a_kadd = lane >> 4;
    const uint32_t b_rowbase = (lane & 7) + ((lane & 16) >> 1);
    const int b_kadd = (lane >> 3) & 1;

    // Q load (grouped with stage 0's commit)
    #pragma unroll
    for (int i = 0; i < 8; i++) {
        int c = i * 256 + tid;
        uint32_t row = (c >> 2) & 127, slot = c & 3, kc = c >> 9;
        size_t src = ((size_t)(b * SEQ + q0 + row)) * EMB + h * HDIM + kc * 32 + slot * 8;
        uint32_t dst = base + kc * 8192 + tile_off(row, slot);
        CP_ASYNC16(dst, Qhi + src);
        CP_ASYNC16(dst + 32768, Qlo + src);
    }

    auto issueKV = [&](int kt) {
        const int k0 = kt * 64;
        const uint32_t stg = base + ATTN_Q_BYTES + (kt & 1) * ATTN_STAGE_BYTES;
        #pragma unroll
        for (int i = 0; i < 4; i++) {
            int c = i * 256 + tid;
            {   // K tile: [64 rows][128 cols] -> 4 chunks of [64][32]
                uint32_t row = (c >> 2) & 63, slot = c & 3, kc = c >> 8;
                size_t src = ((size_t)(b * SEQ + k0 + row)) * EMB + h * HDIM + kc * 32 + slot * 8;
                uint32_t dst = stg + kc * 4096 + tile_off(row, slot);
                CP_ASYNC16(dst, Khi + src);
                CP_ASYNC16(dst + 16384, Klo + src);
            }
            {   // Vt tile: [128 d][64 s] -> 2 chunks of [128][32]
                uint32_t row = (c >> 2) & 127, slot = c & 3, sc = c >> 9;
                size_t src = ((size_t)((b * NHEAD + h) * HDIM + row)) * SEQ + k0 + sc * 32 + slot * 8;
                uint32_t dst = stg + 32768 + sc * 8192 + tile_off(row, slot);
                CP_ASYNC16(dst, Vthi + src);
                CP_ASYNC16(dst + 16384, Vtlo + src);
            }
        }
        CP_COMMIT();
    };

    issueKV(0);

    float oacc[16][4];
    #pragma unroll
    for (int nt = 0; nt < 16; nt++)
        #pragma unroll
        for (int e = 0; e < 4; e++) oacc[nt][e] = 0.0f;
    float m0 = -1e30f, m1 = -1e30f, l0 = 0.0f, l1 = 0.0f;

    const int r0g = q0 + wm0 + g;

    for (int kt = 0; kt < ntiles; kt++) {
        if (kt + 1 < ntiles) { issueKV(kt + 1); CP_WAIT1(); }
        else                 { CP_WAIT0(); }
        __syncthreads();

        const int k0 = kt * 64;
        const uint32_t stg = base + ATTN_Q_BYTES + (kt & 1) * ATTN_STAGE_BYTES;

        // fully-masked warp-tile: contribution is exactly zero -> skip compute
        if (k0 <= q0 + wm0 + 15) {

        // ---- S = Q K^T (3-term split) ----
        float sacc[8][4];
        #pragma unroll
        for (int nt = 0; nt < 8; nt++)
            #pragma unroll
            for (int e = 0; e < 4; e++) sacc[nt][e] = 0.0f;

        #pragma unroll
        for (int ks = 0; ks < 8; ks++) {
            uint32_t ah[4], al[4];
            uint32_t qa = base + (ks >> 1) * 8192 +
                          tile_off(a_row, (uint32_t)((ks & 1) * 2 + a_kadd));
            LDSM4(ah, qa);
            LDSM4(al, qa + 32768);
            #pragma unroll
            for (int np = 0; np < 4; np++) {
                uint32_t rh[4], rl[4];
                uint32_t ka = stg + (ks >> 1) * 4096 +
                              tile_off(np * 16 + b_rowbase, (uint32_t)((ks & 1) * 2 + b_kadd));
                LDSM4(rh, ka);
                LDSM4(rl, ka + 16384);
                uint32_t bh0[2] = {rh[0], rh[1]}, bh1[2] = {rh[2], rh[3]};
                uint32_t bl0[2] = {rl[0], rl[1]}, bl1[2] = {rl[2], rl[3]};
                MMA16816(sacc[np*2],   ah, bh0);
                MMA16816(sacc[np*2],   ah, bl0);
                MMA16816(sacc[np*2],   al, bh0);
                MMA16816(sacc[np*2+1], ah, bh1);
                MMA16816(sacc[np*2+1], ah, bl1);
                MMA16816(sacc[np*2+1], al, bh1);
            }
        }

        // ---- scale + causal mask ----
        #pragma unroll
        for (int nt = 0; nt < 8; nt++)
            #pragma unroll
            for (int e = 0; e < 4; e++) sacc[nt][e] *= ATT_SCALE;

        if (k0 + 63 > q0 + wm0) {
            #pragma unroll
            for (int nt = 0; nt < 8; nt++) {
                int c0 = k0 + nt * 8 + t4 * 2;
                if (c0     > r0g)     sacc[nt][0] = -1e30f;
                if (c0 + 1 > r0g)     sacc[nt][1] = -1e30f;
                if (c0     > r0g + 8) sacc[nt][2] = -1e30f;
                if (c0 + 1 > r0g + 8) sacc[nt][3] = -1e30f;
            }
        }

        // ---- online softmax (rows g and g+8) ----
        float mx0 = -1e30f, mx1 = -1e30f;
        #pragma unroll
        for (int nt = 0; nt < 8; nt++) {
            mx0 = fmaxf(mx0, fmaxf(sacc[nt][0], sacc[nt][1]));
            mx1 = fmaxf(mx1, fmaxf(sacc[nt][2], sacc[nt][3]));
        }
        mx0 = fmaxf(mx0, __shfl_xor_sync(0xffffffffu, mx0, 1));
        mx0 = fmaxf(mx0, __shfl_xor_sync(0xffffffffu, mx0, 2));
        mx1 = fmaxf(mx1, __shfl_xor_sync(0xffffffffu, mx1, 1));
        mx1 = fmaxf(mx1, __shfl_xor_sync(0xffffffffu, mx1, 2));
        float mn0 = fmaxf(m0, mx0), mn1 = fmaxf(m1, mx1);
        float sf0 = __expf(m0 - mn0), sf1 = __expf(m1 - mn1);
        m0 = mn0; m1 = mn1;
        float sum0 = 0.0f, sum1 = 0.0f;
        #pragma unroll
        for (int nt = 0; nt < 8; nt++) {
            sacc[nt][0] = __expf(sacc[nt][0] - mn0); sum0 += sacc[nt][0];
            sacc[nt][1] = __expf(sacc[nt][1] - mn0); sum0 += sacc[nt][1];
            sacc[nt][2] = __expf(sacc[nt][2] - mn1); sum1 += sacc[nt][2];
            sacc[nt][3] = __expf(sacc[nt][3] - mn1); sum1 += sacc[nt][3];
        }
        sum0 += __shfl_xor_sync(0xffffffffu, sum0, 1);
        sum0 += __shfl_xor_sync(0xffffffffu, sum0, 2);
        sum1 += __shfl_xor_sync(0xffffffffu, sum1, 1);
        sum1 += __shfl_xor_sync(0xffffffffu, sum1, 2);
        l0 = l0 * sf0 + sum0;
        l1 = l1 * sf1 + sum1;
        #pragma unroll
        for (int nt = 0; nt < 16; nt++) {
            oacc[nt][0] *= sf0; oacc[nt][1] *= sf0;
            oacc[nt][2] *= sf1; oacc[nt][3] *= sf1;
        }

        // ---- P fragments (acc -> A operand, hi/lo split, in-register) ----
        uint32_t pha[4][4], pla[4][4];
        #pragma unroll
        for (int kp = 0; kp < 4; kp++) {
            #pragma unroll
            for (int half = 0; half < 2; half++) {
                int j = 2 * kp + half;
                #pragma unroll
                for (int rr = 0; rr < 2; rr++) {
                    float p0 = sacc[j][rr * 2 + 0];
                    float p1 = sacc[j][rr * 2 + 1];
                    __nv_bfloat16 h0 = __float2bfloat16(p0);
                    __nv_bfloat16 h1 = __float2bfloat16(p1);
                    pha[kp][half * 2 + rr] = pack_bf16x2(h0, h1);
                    pla[kp][half * 2 + rr] = pack_bf16x2(
                        __float2bfloat16(p0 - __bfloat162float(h0)),
                        __float2bfloat16(p1 - __bfloat162float(h1)));
                }
            }
        }

        // ---- O += P V (3-term split); Vt non-trans LDSM ----
        #pragma unroll
        for (int kp = 0; kp < 4; kp++) {
            #pragma unroll
            for (int nb = 0; nb < 8; nb++) {
                uint32_t rh[4], rl[4];
                uint32_t va = stg + 32768 + (kp >> 1) * 8192 +
                              tile_off(nb * 16 + b_rowbase, (uint32_t)((kp & 1) * 2 + b_kadd));
                LDSM4(rh, va);
                LDSM4(rl, va + 16384);
                uint32_t bh0[2] = {rh[0], rh[1]}, bh1[2] = {rh[2], rh[3]};
                uint32_t bl0[2] = {rl[0], rl[1]}, bl1[2] = {rl[2], rl[3]};
                MMA16816(oacc[nb*2],   pha[kp], bh0);
                MMA16816(oacc[nb*2],   pha[kp], bl0);
                MMA16816(oacc[nb*2],   pla[kp], bh0);
                MMA16816(oacc[nb*2+1], pha[kp], bh1);
                MMA16816(oacc[nb*2+1], pha[kp], bl1);
                MMA16816(oacc[nb*2+1], pla[kp], bh1);
            }
        }

        } // end active warp-tile

        __syncthreads();
    }

    // ---- epilogue: write Yhi/Ylo bf16 split ----
    float inv0 = 1.0f / l0, inv1 = 1.0f / l1;
    int r0 = q0 + wm0 + g, r1 = r0 + 8;
    #pragma unroll
    for (int nt = 0; nt < 16; nt++) {
        int col = h * HDIM + nt * 8 + t4 * 2;
        size_t o0 = (size_t)(b * SEQ + r0) * EMB + col;
        size_t o1 = (size_t)(b * SEQ + r1) * EMB + col;
        __nv_bfloat16 h0, h1, lo0, lo1;
        split1(oacc[nt][0] * inv0, h0, lo0);
        split1(oacc[nt][1] * inv0, h1, lo1);
        *(uint32_t*)(Yhi + o0) = pack_bf16x2(h0, h1);
        *(uint32_t*)(Ylo + o0) = pack_bf16x2(lo0, lo1);
        split1(oacc[nt][2] * inv1, h0, lo0);
        split1(oacc[nt][3] * inv1, h1, lo1);
        *(uint32_t*)(Yhi + o1) = pack_bf16x2(h0, h1);
        *(uint32_t*)(Ylo + o1) = pack_bf16x2(lo0, lo1);
    }
}

// ---------------------------------------------------------------------------
// Launch
// ---------------------------------------------------------------------------
extern "C" void kernel_launch(void* const* d_in, const int* in_sizes, int n_in,
                              void* d_out, int out_size) {
    const float* x  = (const float*)d_in[0];
    const float* wq = (const float*)d_in[1];
    const float* wk = (const float*)d_in[2];
    const float* wv = (const float*)d_in[3];
    const float* wo = (const float*)d_in[4];
    float* out = (float*)d_out;

    float *cp, *sp;
    __nv_bfloat16 *ahi, *alo, *whi, *wlo;
    __nv_bfloat16 *qhi, *qlo, *khi, *klo, *vhi, *vlo, *vthi, *vtlo, *yhi, *ylo;
    cudaGetSymbolAddress((void**)&cp, g_cos);
    cudaGetSymbolAddress((void**)&sp, g_sin);
    cudaGetSymbolAddress((void**)&ahi, g_Ahi);
    cudaGetSymbolAddress((void**)&alo, g_Alo);
    cudaGetSymbolAddress((void**)&whi, g_Whi);
    cudaGetSymbolAddress((void**)&wlo, g_Wlo);
    cudaGetSymbolAddress((void**)&qhi, g_Qhi);
    cudaGetSymbolAddress((void**)&qlo, g_Qlo);
    cudaGetSymbolAddress((void**)&khi, g_Khi);
    cudaGetSymbolAddress((void**)&klo, g_Klo);
    cudaGetSymbolAddress((void**)&vhi, g_Vhi);
    cudaGetSymbolAddress((void**)&vlo, g_Vlo);
    cudaGetSymbolAddress((void**)&vthi, g_Vthi);
    cudaGetSymbolAddress((void**)&vtlo, g_Vtlo);
    cudaGetSymbolAddress((void**)&yhi, g_Yhi);
    cudaGetSymbolAddress((void**)&ylo, g_Ylo);

    cudaFuncSetAttribute(qkv_gemm, cudaFuncAttributeMaxDynamicSharedMemorySize,
                         GEMM_SMEM_BYTES);
    cudaFuncSetAttribute(out_gemm, cudaFuncAttributeMaxDynamicSharedMemorySize,
                         GEMM_SMEM_BYTES);
    cudaFuncSetAttribute(attn_mma, cudaFuncAttributeMaxDynamicSharedMemorySize,
                         ATTN_SMEM_BYTES);

    rope_table_kernel<<<(SEQ * (HDIM/2) + 255) / 256, 256>>>(cp, sp);

    // fused split: x + 4 weights
    {
        int n4max = MTOT * GK / 4;
        dim3 sg((n4max + 255) / 256, 1, 5);
        split_multi<<<sg, 256>>>(x, wq, wk, wv, wo, ahi, alo, whi, wlo);
    }

    // QKV projections + RoPE fused
    dim3 gg(GN / 128, MTOT / 128, 3);
    qkv_gemm<<<gg, 256, GEMM_SMEM_BYTES>>>(ahi, alo, whi, wlo, cp, sp,
                                           qhi, qlo, khi, klo, vhi, vlo);

    // V bf16 transpose -> [b,h,d,s]
    {
        dim3 tg(32, 8);
        dim3 vtg(SEQ / 32, HDIM / 32, BATCH * NHEAD);
        vtrans_bf16<<<vtg, tg>>>(vhi, vlo, vthi, vtlo);
    }

    // Tensor-core flash attention (heavy CTAs first)
    dim3 ag(SEQ / 128, NHEAD, BATCH);
    attn_mma<<<ag, 256, ATTN_SMEM_BYTES>>>(qhi, qlo, khi, klo, vthi, vtlo, yhi, ylo);

    // out = y @ wo
    dim3 og(GN / 128, MTOT / 128);
    out_gemm<<<og, 256, GEMM_SMEM_BYTES>>>(yhi, ylo,
                                           whi + (size_t)3 * GN * GK,
                                           wlo + (size_t)3 * GN * GK, out);
}

// round 17
// speedup vs baseline: 1.5336x; 1.5336x over previous
#include <cuda_runtime.h>
#include <cuda_fp16.h>
#include <math.h>
#include <stdint.h>

// Problem constants
#define BATCH   2
#define SEQ     2048
#define EMB     2048
#define NHEAD   16
#define HDIM    128
#define MTOT    (BATCH*SEQ)          // 4096
#define GK      2048
#define GN      2048
#define ATT_SCALE 0.08838834764831845f  // 1/sqrt(128)

// Scratch (device globals: allocation-free)
__device__ float g_cos[SEQ*(HDIM/2)];
__device__ float g_sin[SEQ*(HDIM/2)];
__device__ __half g_Ahi[MTOT*GK];
__device__ __half g_Alo[MTOT*GK];
__device__ __half g_Whi[4*GN*GK];   // wq,wk,wv,wo in [K,N] (hi only)
__device__ __half g_Qhi[MTOT*EMB];
__device__ __half g_Qlo[MTOT*EMB];
__device__ __half g_Khi[MTOT*EMB];  // K single fp16
__device__ __half g_Vhi[MTOT*EMB];  // [b,s,h,d]
__device__ __half g_Vthi[MTOT*EMB]; // [b,h,d,s]
__device__ __half g_Yhi[MTOT*EMB];
__device__ __half g_Ylo[MTOT*EMB];

// ============================================================================
// PTX helpers (portable sm_80+ only)
// ============================================================================
__device__ __forceinline__ uint32_t smem_u32(const void* p) {
    uint32_t a;
    asm("{ .reg .u64 t; cvta.to.shared.u64 t, %1; cvt.u32.u64 %0, t; }"
        : "=r"(a) : "l"(p));
    return a;
}

#define CP_ASYNC16(dst, src) \
    asm volatile("cp.async.cg.shared.global [%0], [%1], 16;" \
                 :: "r"(dst), "l"(src) : "memory")
#define CP_COMMIT() asm volatile("cp.async.commit_group;" ::: "memory")
#define CP_WAIT2()  asm volatile("cp.async.wait_group 2;" ::: "memory")
#define CP_WAIT1()  asm volatile("cp.async.wait_group 1;" ::: "memory")
#define CP_WAIT0()  asm volatile("cp.async.wait_group 0;" ::: "memory")

#define LDSM4(r, addr)                                                         \
    asm volatile("ldmatrix.sync.aligned.m8n8.x4.shared.b16 {%0,%1,%2,%3}, [%4];" \
                 : "=r"((r)[0]), "=r"((r)[1]), "=r"((r)[2]), "=r"((r)[3])      \
                 : "r"(addr))

#define LDSM4T(r, addr)                                                        \
    asm volatile("ldmatrix.sync.aligned.m8n8.x4.trans.shared.b16 {%0,%1,%2,%3}, [%4];" \
                 : "=r"((r)[0]), "=r"((r)[1]), "=r"((r)[2]), "=r"((r)[3])      \
                 : "r"(addr))

#define MMA16816(d, a, b)                                                      \
    asm volatile(                                                              \
        "mma.sync.aligned.m16n8k16.row.col.f32.f16.f16.f32 "                   \
        "{%0,%1,%2,%3}, {%4,%5,%6,%7}, {%8,%9}, {%0,%1,%2,%3};"                \
        : "+f"((d)[0]), "+f"((d)[1]), "+f"((d)[2]), "+f"((d)[3])               \
        : "r"((a)[0]), "r"((a)[1]), "r"((a)[2]), "r"((a)[3]),                  \
          "r"((b)[0]), "r"((b)[1]))

__device__ __forceinline__ uint32_t pack_h2(__half x, __half y) {
    __half2 v = __halves2half2(x, y);
    return *reinterpret_cast<uint32_t*>(&v);
}

// A tile: [rows][64B], 4 slots of 16B, swizzle period-8
__device__ __forceinline__ uint32_t tile_off(uint32_t row, uint32_t slot) {
    return row * 64 + ((slot ^ ((row >> 1) & 3)) << 4);
}
// B tile: [rows][256B], 16 slots of 16B, swizzle period-8
__device__ __forceinline__ uint32_t btile_off(uint32_t row, uint32_t slot) {
    return row * 256 + ((slot ^ (row & 7)) << 4);
}

__device__ __forceinline__ void split1(float v, __half& h, __half& l) {
    h = __float2half(v);
    l = __float2half(v - __half2float(h));
}

// ============================================================================
// Fused split: z=0 -> x hi/lo, z=1..4 -> weights hi only ([K,N])
// ============================================================================
__global__ void split_multi(const float* __restrict__ x,
                            const float* __restrict__ wq, const float* __restrict__ wk,
                            const float* __restrict__ wv, const float* __restrict__ wo,
                            __half* __restrict__ ahi, __half* __restrict__ alo,
                            __half* __restrict__ whi) {
    int z = blockIdx.z;
    const float* src;
    __half *dh, *dl = nullptr;
    int n4;
    if (z == 0) { src = x; dh = ahi; dl = alo; n4 = MTOT * GK / 4; }
    else {
        src = (z == 1) ? wq : (z == 2) ? wk : (z == 3) ? wv : wo;
        dh = whi + (size_t)(z - 1) * GN * GK;
        n4 = GN * GK / 4;
    }
    int i = blockIdx.x * blockDim.x + threadIdx.x;
    if (i >= n4) return;
    float4 v = ((const float4*)src)[i];
    __half h0 = __float2half(v.x), h1 = __float2half(v.y);
    __half h2 = __float2half(v.z), h3 = __float2half(v.w);
    uint2* hp = (uint2*)dh;
    hp[i] = make_uint2(pack_h2(h0, h1), pack_h2(h2, h3));
    if (z == 0) {
        __half l0 = __float2half(v.x - __half2float(h0));
        __half l1 = __float2half(v.y - __half2float(h1));
        __half l2 = __float2half(v.z - __half2float(h2));
        __half l3 = __float2half(v.w - __half2float(h3));
        uint2* lp = (uint2*)dl;
        lp[i] = make_uint2(pack_h2(l0, l1), pack_h2(l2, l3));
    }
}

// ---------------------------------------------------------------------------
// RoPE table
// ---------------------------------------------------------------------------
__global__ void rope_table_kernel(float* ct, float* st) {
    int idx = blockIdx.x * blockDim.x + threadIdx.x;
    if (idx >= SEQ * (HDIM/2)) return;
    int s = idx >> 6;
    int j = idx & 63;
    float inv = powf(10000.0f, -((float)(2*j)) / 128.0f);
    float a = (float)s * inv;
    ct[idx] = cosf(a);
    st[idx] = sinf(a);
}

// ---------------------------------------------------------------------------
// V fp16 [b,s,h,d] -> Vt fp16 [b,h,d,s]
// ---------------------------------------------------------------------------
__global__ void vtrans_f16(const __half* __restrict__ V, __half* __restrict__ T) {
    __shared__ __half t[32][34];
    int s0 = blockIdx.x * 32, d0 = blockIdx.y * 32, bh = blockIdx.z;
    int b = bh >> 4, h = bh & 15;
    int tx = threadIdx.x, ty = threadIdx.y;
    #pragma unroll
    for (int j = 0; j < 32; j += 8)
        t[ty + j][tx] = V[(size_t)(b * SEQ + s0 + ty + j) * EMB + h * HDIM + d0 + tx];
    __syncthreads();
    #pragma unroll
    for (int j = 0; j < 32; j += 8)
        T[(size_t)(bh * HDIM + d0 + ty + j) * SEQ + s0 + tx] = t[tx][ty + j];
}

// ============================================================================
// Shared GEMM mainloop: acc = (Ahi+Alo)[M,K] * Bhi[K,N]  (fp16 2-term)
// 128x128 CTA tile, BK=32, 8 warps (2x4), 4-stage cp.async pipeline.
// Stage (24KB): Ahi@0, Alo@8192, Bhi@16384
// ============================================================================
#define NKB (GK / 32)
#define G_STAGE 24576
#define GEMM_SMEM_BYTES (4*G_STAGE)   // 96KB -> 2 CTAs/SM

__device__ __forceinline__ void gemm_mainloop(
    const __half* __restrict__ Ahi, const __half* __restrict__ Alo,
    const __half* __restrict__ Bhi,
    uint32_t base, int tid, int m0, int n0, float (&acc)[4][4][4]) {
    const int wid  = tid >> 5;
    const int lane = tid & 31;
    const int wm = wid >> 2;
    const int wn = wid & 3;

    #pragma unroll
    for (int mt = 0; mt < 4; mt++)
        #pragma unroll
        for (int nt = 0; nt < 4; nt++)
            #pragma unroll
            for (int e = 0; e < 4; e++) acc[mt][nt][e] = 0.0f;

    const uint32_t a_row  = wm * 64 + (lane & 15);
    const int      a_kadd = lane >> 4;
    const uint32_t b_row16 = lane & 15;
    const uint32_t b_sadd  = lane >> 4;

    auto issue = [&](int kb) {
        const int kcol = kb * 32;
        const uint32_t stg = base + (kb & 3) * G_STAGE;
        #pragma unroll
        for (int i = 0; i < 2; i++) {
            int c = i * 256 + tid;
            {   // A: row 0..127, slot 0..3 (hi + lo)
                uint32_t row = c >> 2, slot = c & 3;
                const __half* s  = Ahi + (size_t)(m0 + row) * GK + kcol + slot * 8;
                const __half* s2 = Alo + (size_t)(m0 + row) * GK + kcol + slot * 8;
                uint32_t d = stg + tile_off(row, slot);
                CP_ASYNC16(d, s);
                CP_ASYNC16(d + 8192, s2);
            }
            {   // B: row 0..31 (k), slot 0..15 (n16), hi only
                uint32_t row = c >> 4, slot = c & 15;
                const __half* s = Bhi + (size_t)(kcol + row) * GN + n0 + slot * 8;
                uint32_t d = stg + 16384 + btile_off(row, slot);
                CP_ASYNC16(d, s);
            }
        }
        CP_COMMIT();
    };

    issue(0);
    issue(1);
    issue(2);

    for (int kb = 0; kb < NKB; kb++) {
        int rem = NKB - 1 - kb;
        if (rem >= 2)      CP_WAIT2();
        else if (rem == 1) CP_WAIT1();
        else               CP_WAIT0();
        __syncthreads();
        if (kb + 3 < NKB) issue(kb + 3);

        const uint32_t st = base + (kb & 3) * G_STAGE;

        #pragma unroll
        for (int ks = 0; ks < 2; ks++) {
            uint32_t ahi[4][4], alo[4][4], bhi[4][2];
            #pragma unroll
            for (int mt = 0; mt < 4; mt++) {
                uint32_t row = a_row + mt * 16;
                uint32_t ad  = st + tile_off(row, (uint32_t)(ks * 2 + a_kadd));
                LDSM4(ahi[mt], ad);
                LDSM4(alo[mt], ad + 8192);
            }
            #pragma unroll
            for (int np = 0; np < 2; np++) {
                uint32_t row = ks * 16 + b_row16;
                uint32_t slot = wn * 4 + np * 2 + b_sadd;
                uint32_t bd = st + 16384 + btile_off(row, slot);
                uint32_t r[4];
                LDSM4T(r, bd);
                bhi[np*2][0] = r[0]; bhi[np*2][1] = r[1];
                bhi[np*2+1][0] = r[2]; bhi[np*2+1][1] = r[3];
            }
            #pragma unroll
            for (int mt = 0; mt < 4; mt++)
                #pragma unroll
                for (int nt = 0; nt < 4; nt++) {
                    MMA16816(acc[mt][nt], ahi[mt], bhi[nt]);
                    MMA16816(acc[mt][nt], alo[mt], bhi[nt]);
                }
        }
    }
}

// ---- QKV GEMM: z=0 Q(rope, hi/lo), z=1 K(rope, hi), z=2 V(hi) ----
__global__ __launch_bounds__(256) void qkv_gemm(
    const __half* __restrict__ Ahi, const __half* __restrict__ Alo,
    const __half* __restrict__ Whi,
    const float* __restrict__ ct, const float* __restrict__ st,
    __half* __restrict__ Qhi, __half* __restrict__ Qlo,
    __half* __restrict__ Khi, __half* __restrict__ Vhi) {
    extern __shared__ char smraw[];
    const uint32_t base = smem_u32(smraw);
    const int tid = threadIdx.x;
    const int m0 = blockIdx.y * 128;
    const int n0 = blockIdx.x * 128;
    const int z  = blockIdx.z;
    const __half* Bh = Whi + (size_t)z * GN * GK;

    float acc[4][4][4];
    gemm_mainloop(Ahi, Alo, Bh, base, tid, m0, n0, acc);

    const int wid = tid >> 5, lane = tid & 31;
    const int wm = wid >> 2, wn = wid & 3;
    const int r0 = m0 + wm * 64 + (lane >> 2);
    const int c0 = n0 + wn * 32 + (lane & 3) * 2;

    #pragma unroll
    for (int mt = 0; mt < 4; mt++)
        #pragma unroll
        for (int nt = 0; nt < 4; nt++) {
            int col = c0 + nt * 8;
            int j = (col & 127) >> 1;
            #pragma unroll
            for (int rr = 0; rr < 2; rr++) {
                int row = r0 + mt * 16 + rr * 8;
                float x1 = acc[mt][nt][rr*2], x2 = acc[mt][nt][rr*2+1];
                if (z < 2) {   // RoPE for Q, K
                    int s = row & (SEQ - 1);
                    float cv = ct[(s << 6) + j], sv = st[(s << 6) + j];
                    float n1 = x1 * cv - x2 * sv;
                    float n2 = x1 * sv + x2 * cv;
                    x1 = n1; x2 = n2;
                }
                size_t o = (size_t)row * EMB + col;
                if (z == 0) {
                    __half h1, h2, l1, l2;
                    split1(x1, h1, l1); split1(x2, h2, l2);
                    *(uint32_t*)(Qhi + o) = pack_h2(h1, h2);
                    *(uint32_t*)(Qlo + o) = pack_h2(l1, l2);
                } else if (z == 1) {
                    *(uint32_t*)(Khi + o) = pack_h2(__float2half(x1), __float2half(x2));
                } else {
                    *(uint32_t*)(Vhi + o) = pack_h2(__float2half(x1), __float2half(x2));
                }
            }
        }
}

// ---- Output GEMM: fp32 epilogue ----
__global__ __launch_bounds__(256) void out_gemm(
    const __half* __restrict__ Ahi, const __half* __restrict__ Alo,
    const __half* __restrict__ Bhi, float* __restrict__ C) {
    extern __shared__ char smraw[];
    const uint32_t base = smem_u32(smraw);
    const int tid = threadIdx.x;
    const int m0 = blockIdx.y * 128;
    const int n0 = blockIdx.x * 128;

    float acc[4][4][4];
    gemm_mainloop(Ahi, Alo, Bhi, base, tid, m0, n0, acc);

    const int wid = tid >> 5, lane = tid & 31;
    const int wm = wid >> 2, wn = wid & 3;
    const int r0  = m0 + wm * 64 + (lane >> 2);
    const int col = n0 + wn * 32 + (lane & 3) * 2;
    #pragma unroll
    for (int mt = 0; mt < 4; mt++)
        #pragma unroll
        for (int nt = 0; nt < 4; nt++) {
            float* d = acc[mt][nt];
            size_t o0 = (size_t)(r0 + mt * 16)     * GN + col + nt * 8;
            size_t o1 = (size_t)(r0 + mt * 16 + 8) * GN + col + nt * 8;
            *(float2*)(C + o0) = make_float2(d[0], d[1]);
            *(float2*)(C + o1) = make_float2(d[2], d[3]);
        }
}

// ============================================================================
// Tensor-core causal flash attention (fp16 2-term: left operands split).
// BQ=128 (8 warps x m16), BK=64, double-buffered K/Vt (hi only), Q hi/lo.
// smem: Qhi@0 Qlo@32768; stage s @ 65536+s*32768: Khi(16K) Vthi(16K)
// ============================================================================
#define ATTN_Q_BYTES     65536
#define ATTN_STAGE_BYTES 32768
#define ATTN_SMEM_BYTES  (ATTN_Q_BYTES + 2*ATTN_STAGE_BYTES)  // 131072

__global__ __launch_bounds__(256, 1) void attn_mma(
    const __half* __restrict__ Qhi, const __half* __restrict__ Qlo,
    const __half* __restrict__ Khi, const __half* __restrict__ Vthi,
    __half* __restrict__ Yhi, __half* __restrict__ Ylo) {
    extern __shared__ char smraw[];
    const uint32_t base = smem_u32(smraw);
    const int tid = threadIdx.x, wid = tid >> 5, lane = tid & 31;
    const int qb = gridDim.x - 1 - blockIdx.x;   // heavy CTAs first
    const int h = blockIdx.y, b = blockIdx.z;
    const int q0 = qb * 128;
    const int wm0 = wid * 16;
    const int g = lane >> 2, t4 = lane & 3;
    const int ntiles = 2 * qb + 2;

    const uint32_t a_row = wm0 + (lane & 15);
    const int a_kadd = lane >> 4;
    const uint32_t b_rowbase = (lane & 7) + ((lane & 16) >> 1);
    const int b_kadd = (lane >> 3) & 1;

    // Q load (hi+lo), grouped with stage 0's commit
    #pragma unroll
    for (int i = 0; i < 8; i++) {
        int c = i * 256 + tid;
        uint32_t row = (c >> 2) & 127, slot = c & 3, kc = c >> 9;
        size_t src = ((size_t)(b * SEQ + q0 + row)) * EMB + h * HDIM + kc * 32 + slot * 8;
        uint32_t dst = base + kc * 8192 + tile_off(row, slot);
        CP_ASYNC16(dst, Qhi + src);
        CP_ASYNC16(dst + 32768, Qlo + src);
    }

    auto issueKV = [&](int kt) {
        const int k0 = kt * 64;
        const uint32_t stg = base + ATTN_Q_BYTES + (kt & 1) * ATTN_STAGE_BYTES;
        #pragma unroll
        for (int i = 0; i < 4; i++) {
            int c = i * 256 + tid;
            {   // K tile: [64 rows][128 cols] -> 4 chunks of [64][32], hi only
                uint32_t row = (c >> 2) & 63, slot = c & 3, kc = c >> 8;
                size_t src = ((size_t)(b * SEQ + k0 + row)) * EMB + h * HDIM + kc * 32 + slot * 8;
                CP_ASYNC16(stg + kc * 4096 + tile_off(row, slot), Khi + src);
            }
            {   // Vt tile: [128 d][64 s] -> 2 chunks of [128][32], hi only
                uint32_t row = (c >> 2) & 127, slot = c & 3, sc = c >> 9;
                size_t src = ((size_t)((b * NHEAD + h) * HDIM + row)) * SEQ + k0 + sc * 32 + slot * 8;
                CP_ASYNC16(stg + 16384 + sc * 8192 + tile_off(row, slot), Vthi + src);
            }
        }
        CP_COMMIT();
    };

    issueKV(0);

    float oacc[16][4];
    #pragma unroll
    for (int nt = 0; nt < 16; nt++)
        #pragma unroll
        for (int e = 0; e < 4; e++) oacc[nt][e] = 0.0f;
    float m0 = -1e30f, m1 = -1e30f, l0 = 0.0f, l1 = 0.0f;

    const int r0g = q0 + wm0 + g;

    for (int kt = 0; kt < ntiles; kt++) {
        if (kt + 1 < ntiles) { issueKV(kt + 1); CP_WAIT1(); }
        else                 { CP_WAIT0(); }
        __syncthreads();

        const int k0 = kt * 64;
        const uint32_t stg = base + ATTN_Q_BYTES + (kt & 1) * ATTN_STAGE_BYTES;

        // fully-masked warp-tile: contribution exactly zero -> skip
        if (k0 <= q0 + wm0 + 15) {

        // ---- S = (Qhi+Qlo) Khi^T ----
        float sacc[8][4];
        #pragma unroll
        for (int nt = 0; nt < 8; nt++)
            #pragma unroll
            for (int e = 0; e < 4; e++) sacc[nt][e] = 0.0f;

        #pragma unroll
        for (int ks = 0; ks < 8; ks++) {
            uint32_t ah[4], al[4];
            uint32_t qa = base + (ks >> 1) * 8192 +
                          tile_off(a_row, (uint32_t)((ks & 1) * 2 + a_kadd));
            LDSM4(ah, qa);
            LDSM4(al, qa + 32768);
            #pragma unroll
            for (int np = 0; np < 4; np++) {
                uint32_t rh[4];
                uint32_t ka = stg + (ks >> 1) * 4096 +
                              tile_off(np * 16 + b_rowbase, (uint32_t)((ks & 1) * 2 + b_kadd));
                LDSM4(rh, ka);
                uint32_t bh0[2] = {rh[0], rh[1]}, bh1[2] = {rh[2], rh[3]};
                MMA16816(sacc[np*2],   ah, bh0);
                MMA16816(sacc[np*2],   al, bh0);
                MMA16816(sacc[np*2+1], ah, bh1);
                MMA16816(sacc[np*2+1], al, bh1);
            }
        }

        // ---- scale + causal mask ----
        #pragma unroll
        for (int nt = 0; nt < 8; nt++)
            #pragma unroll
            for (int e = 0; e < 4; e++) sacc[nt][e] *= ATT_SCALE;

        if (k0 + 63 > q0 + wm0) {
            #pragma unroll
            for (int nt = 0; nt < 8; nt++) {
                int c0 = k0 + nt * 8 + t4 * 2;
                if (c0     > r0g)     sacc[nt][0] = -1e30f;
                if (c0 + 1 > r0g)     sacc[nt][1] = -1e30f;
                if (c0     > r0g + 8) sacc[nt][2] = -1e30f;
                if (c0 + 1 > r0g + 8) sacc[nt][3] = -1e30f;
            }
        }

        // ---- online softmax (rows g and g+8) ----
        float mx0 = -1e30f, mx1 = -1e30f;
        #pragma unroll
        for (int nt = 0; nt < 8; nt++) {
            mx0 = fmaxf(mx0, fmaxf(sacc[nt][0], sacc[nt][1]));
            mx1 = fmaxf(mx1, fmaxf(sacc[nt][2], sacc[nt][3]));
        }
        mx0 = fmaxf(mx0, __shfl_xor_sync(0xffffffffu, mx0, 1));
        mx0 = fmaxf(mx0, __shfl_xor_sync(0xffffffffu, mx0, 2));
        mx1 = fmaxf(mx1, __shfl_xor_sync(0xffffffffu, mx1, 1));
        mx1 = fmaxf(mx1, __shfl_xor_sync(0xffffffffu, mx1, 2));
        float mn0 = fmaxf(m0, mx0), mn1 = fmaxf(m1, mx1);
        float sf0 = __expf(m0 - mn0), sf1 = __expf(m1 - mn1);
        m0 = mn0; m1 = mn1;
        float sum0 = 0.0f, sum1 = 0.0f;
        #pragma unroll
        for (int nt = 0; nt < 8; nt++) {
            sacc[nt][0] = __expf(sacc[nt][0] - mn0); sum0 += sacc[nt][0];
            sacc[nt][1] = __expf(sacc[nt][1] - mn0); sum0 += sacc[nt][1];
            sacc[nt][2] = __expf(sacc[nt][2] - mn1); sum1 += sacc[nt][2];
            sacc[nt][3] = __expf(sacc[nt][3] - mn1); sum1 += sacc[nt][3];
        }
        sum0 += __shfl_xor_sync(0xffffffffu, sum0, 1);
        sum0 += __shfl_xor_sync(0xffffffffu, sum0, 2);
        sum1 += __shfl_xor_sync(0xffffffffu, sum1, 1);
        sum1 += __shfl_xor_sync(0xffffffffu, sum1, 2);
        l0 = l0 * sf0 + sum0;
        l1 = l1 * sf1 + sum1;
        #pragma unroll
        for (int nt = 0; nt < 16; nt++) {
            oacc[nt][0] *= sf0; oacc[nt][1] *= sf0;
            oacc[nt][2] *= sf1; oacc[nt][3] *= sf1;
        }

        // ---- P fragments (hi/lo split in-register) ----
        uint32_t pha[4][4], pla[4][4];
        #pragma unroll
        for (int kp = 0; kp < 4; kp++) {
            #pragma unroll
            for (int half = 0; half < 2; half++) {
                int j = 2 * kp + half;
                #pragma unroll
                for (int rr = 0; rr < 2; rr++) {
                    float p0 = sacc[j][rr * 2 + 0];
                    float p1 = sacc[j][rr * 2 + 1];
                    __half h0, h1, lo0, lo1;
                    split1(p0, h0, lo0);
                    split1(p1, h1, lo1);
                    pha[kp][half * 2 + rr] = pack_h2(h0, h1);
                    pla[kp][half * 2 + rr] = pack_h2(lo0, lo1);
                }
            }
        }

        // ---- O += (Phi+Plo) Vthi ----
        #pragma unroll
        for (int kp = 0; kp < 4; kp++) {
            #pragma unroll
            for (int nb = 0; nb < 8; nb++) {
                uint32_t rh[4];
                uint32_t va = stg + 16384 + (kp >> 1) * 8192 +
                              tile_off(nb * 16 + b_rowbase, (uint32_t)((kp & 1) * 2 + b_kadd));
                LDSM4(rh, va);
                uint32_t bh0[2] = {rh[0], rh[1]}, bh1[2] = {rh[2], rh[3]};
                MMA16816(oacc[nb*2],   pha[kp], bh0);
                MMA16816(oacc[nb*2],   pla[kp], bh0);
                MMA16816(oacc[nb*2+1], pha[kp], bh1);
                MMA16816(oacc[nb*2+1], pla[kp], bh1);
            }
        }

        } // end active warp-tile

        __syncthreads();
    }

    // ---- epilogue: write Yhi/Ylo fp16 split ----
    float inv0 = 1.0f / l0, inv1 = 1.0f / l1;
    int r0 = q0 + wm0 + g, r1 = r0 + 8;
    #pragma unroll
    for (int nt = 0; nt < 16; nt++) {
        int col = h * HDIM + nt * 8 + t4 * 2;
        size_t o0 = (size_t)(b * SEQ + r0) * EMB + col;
        size_t o1 = (size_t)(b * SEQ + r1) * EMB + col;
        __half h0, h1, lo0, lo1;
        split1(oacc[nt][0] * inv0, h0, lo0);
        split1(oacc[nt][1] * inv0, h1, lo1);
        *(uint32_t*)(Yhi + o0) = pack_h2(h0, h1);
        *(uint32_t*)(Ylo + o0) = pack_h2(lo0, lo1);
        split1(oacc[nt][2] * inv1, h0, lo0);
        split1(oacc[nt][3] * inv1, h1, lo1);
        *(uint32_t*)(Yhi + o1) = pack_h2(h0, h1);
        *(uint32_t*)(Ylo + o1) = pack_h2(lo0, lo1);
    }
}

// ---------------------------------------------------------------------------
// Launch
// ---------------------------------------------------------------------------
extern "C" void kernel_launch(void* const* d_in, const int* in_sizes, int n_in,
                              void* d_out, int out_size) {
    const float* x  = (const float*)d_in[0];
    const float* wq = (const float*)d_in[1];
    const float* wk = (const float*)d_in[2];
    const float* wv = (const float*)d_in[3];
    const float* wo = (const float*)d_in[4];
    float* out = (float*)d_out;

    float *cp, *sp;
    __half *ahi, *alo, *whi, *qhi, *qlo, *khi, *vhi, *vthi, *yhi, *ylo;
    cudaGetSymbolAddress((void**)&cp, g_cos);
    cudaGetSymbolAddress((void**)&sp, g_sin);
    cudaGetSymbolAddress((void**)&ahi, g_Ahi);
    cudaGetSymbolAddress((void**)&alo, g_Alo);
    cudaGetSymbolAddress((void**)&whi, g_Whi);
    cudaGetSymbolAddress((void**)&qhi, g_Qhi);
    cudaGetSymbolAddress((void**)&qlo, g_Qlo);
    cudaGetSymbolAddress((void**)&khi, g_Khi);
    cudaGetSymbolAddress((void**)&vhi, g_Vhi);
    cudaGetSymbolAddress((void**)&vthi, g_Vthi);
    cudaGetSymbolAddress((void**)&yhi, g_Yhi);
    cudaGetSymbolAddress((void**)&ylo, g_Ylo);

    cudaFuncSetAttribute(qkv_gemm, cudaFuncAttributeMaxDynamicSharedMemorySize,
                         GEMM_SMEM_BYTES);
    cudaFuncSetAttribute(out_gemm, cudaFuncAttributeMaxDynamicSharedMemorySize,
                         GEMM_SMEM_BYTES);
    cudaFuncSetAttribute(attn_mma, cudaFuncAttributeMaxDynamicSharedMemorySize,
                         ATTN_SMEM_BYTES);

    rope_table_kernel<<<(SEQ * (HDIM/2) + 255) / 256, 256>>>(cp, sp);

    // fused split: x hi/lo + 4 weights hi
    {
        int n4max = MTOT * GK / 4;
        dim3 sg((n4max + 255) / 256, 1, 5);
        split_multi<<<sg, 256>>>(x, wq, wk, wv, wo, ahi, alo, whi);
    }

    // QKV projections + RoPE fused
    dim3 gg(GN / 128, MTOT / 128, 3);
    qkv_gemm<<<gg, 256, GEMM_SMEM_BYTES>>>(ahi, alo, whi, cp, sp,
                                           qhi, qlo, khi, vhi);

    // V fp16 transpose -> [b,h,d,s]
    {
        dim3 tg(32, 8);
        dim3 vtg(SEQ / 32, HDIM / 32, BATCH * NHEAD);
        vtrans_f16<<<vtg, tg>>>(vhi, vthi);
    }

    // Tensor-core flash attention
    dim3 ag(SEQ / 128, NHEAD, BATCH);
    attn_mma<<<ag, 256, ATTN_SMEM_BYTES>>>(qhi, qlo, khi, vthi, yhi, ylo);

    // out = y @ wo
    dim3 og(GN / 128, MTOT / 128);
    out_gemm<<<og, 256, GEMM_SMEM_BYTES>>>(yhi, ylo,
                                           whi + (size_t)3 * GN * GK, out);
}